// round 10
// baseline (speedup 1.0000x reference)
#include <cuda_runtime.h>
#include <cstdint>

// ---------------------------------------------------------------------------
// Scratch (allocation-free: __device__ globals)
// ---------------------------------------------------------------------------
__device__ float  g_qkv[8 * 512 * 3072];          // [B*S, 3D] fp32
__device__ float  g_attn[8 * 512 * 1024];         // [B*S, D]  fp32
__device__ float2 g_a2[4096 * 512];               // A operand, tf32 pair-interleaved
__device__ float2 g_w2[512 * 3072 + 512 * 1024];  // W operands, tf32 pair-interleaved

static __device__ __forceinline__ float cvt_rna_f(float x) {
    uint32_t r;
    asm("cvt.rna.tf32.f32 %0, %1;" : "=r"(r) : "f"(x));
    return __uint_as_float(r);
}

// ---------------------------------------------------------------------------
// prep_A: A[M,1024] fp32 -> A2[M,512] float2, A2[m][g*4+c] = tf32(A[m][g*8+c],
// A[m][g*8+c+4]).  One thread per (m, g) 8-k group.
// ---------------------------------------------------------------------------
__global__ void __launch_bounds__(256) prep_A_kernel(
    const float* __restrict__ A, float2* __restrict__ A2)
{
    const int t = blockIdx.x * 256 + threadIdx.x;
    const int m = t >> 7, g = t & 127;
    const float4 lo = *(const float4*)(A + (size_t)m * 1024 + g * 8);
    const float4 hi = *(const float4*)(A + (size_t)m * 1024 + g * 8 + 4);
    float2* o = A2 + (size_t)m * 512 + g * 4;
    o[0] = make_float2(cvt_rna_f(lo.x), cvt_rna_f(hi.x));
    o[1] = make_float2(cvt_rna_f(lo.y), cvt_rna_f(hi.y));
    o[2] = make_float2(cvt_rna_f(lo.z), cvt_rna_f(hi.z));
    o[3] = make_float2(cvt_rna_f(lo.w), cvt_rna_f(hi.w));
}

// ---------------------------------------------------------------------------
// prep_W: W[1024,N] fp32 -> B2[512,N] float2,
// B2[p][n] = tf32(W[klo][n], W[klo+4][n]), klo = (p/4)*8 + p%4.
// One thread per (p, 4-n chunk).
// ---------------------------------------------------------------------------
__global__ void __launch_bounds__(256) prep_W_kernel(
    const float* __restrict__ W, float2* __restrict__ B2, int N)
{
    const int t = blockIdx.x * 256 + threadIdx.x;
    const int nq = N >> 2;
    const int p = t / nq, n4 = (t % nq) << 2;
    const int klo = ((p >> 2) << 3) + (p & 3);
    const float4 lo = *(const float4*)(W + (size_t)klo * N + n4);
    const float4 hi = *(const float4*)(W + (size_t)(klo + 4) * N + n4);
    float2* o = B2 + (size_t)p * N + n4;
    o[0] = make_float2(cvt_rna_f(lo.x), cvt_rna_f(hi.x));
    o[1] = make_float2(cvt_rna_f(lo.y), cvt_rna_f(hi.y));
    o[2] = make_float2(cvt_rna_f(lo.z), cvt_rna_f(hi.z));
    o[3] = make_float2(cvt_rna_f(lo.w), cvt_rna_f(hi.w));
}

// ---------------------------------------------------------------------------
// TF32 mma.sync GEMM on pair-interleaved operands.
// C[M,N] = A[M,1024] @ W[1024,N] + bias[N]
// Block 128x128x32, 256 thr (8 warps, 2x4), warp tile 64x32, m16n8k8.
// 3-stage cp.async pipeline, one __syncthreads per iter, all-LDS.64 fragments.
// ---------------------------------------------------------------------------
#define AST 20                     // A stage row stride (float2); 40 banks = 8 mod 32
#define BST 132                    // B stage row stride (float2); 264 banks = 8 mod 32
#define A_STG_F2 (128 * AST)       // 2560 float2
#define B_STG_F2 (16 * BST)        // 2112 float2
#define STG_BYTES ((A_STG_F2 + B_STG_F2) * 8)   // 37376 B
#define NST 3
#define GEMM_DSMEM (NST * STG_BYTES)            // 112128 B

static __device__ __forceinline__ void cp_async16(uint32_t s, const void* g) {
    asm volatile("cp.async.cg.shared.global [%0], [%1], 16;\n"
                 :: "r"(s), "l"(g) : "memory");
}

static __device__ __forceinline__ void mma_tf32(float* c, const uint32_t* a,
                                                const uint32_t* b) {
    asm volatile(
        "mma.sync.aligned.m16n8k8.row.col.f32.tf32.tf32.f32 "
        "{%0,%1,%2,%3}, {%4,%5,%6,%7}, {%8,%9}, {%0,%1,%2,%3};"
        : "+f"(c[0]), "+f"(c[1]), "+f"(c[2]), "+f"(c[3])
        : "r"(a[0]), "r"(a[1]), "r"(a[2]), "r"(a[3]), "r"(b[0]), "r"(b[1]));
}

__global__ void __launch_bounds__(256) gemm_tf32i_kernel(
    const float2* __restrict__ A2, const float2* __restrict__ B2,
    const float* __restrict__ bias, float* __restrict__ C, int N)
{
    extern __shared__ char smem[];
    const int tid  = threadIdx.x;
    const int lane = tid & 31;
    const int warp = tid >> 5;
    const int wm   = warp >> 2;          // 0..1
    const int wn   = warp & 3;           // 0..3
    const int bx   = blockIdx.x, by = blockIdx.y;
    const int r0   = lane >> 2;          // 0..7
    const int c0   = lane & 3;           // 0..3

    uint32_t sbase;
    asm("{ .reg .u64 t; cvta.to.shared.u64 t, %1; cvt.u32.u64 %0, t; }"
        : "=r"(sbase) : "l"(smem));

    // Copy mapping
    const int am   = tid >> 1;           // A row 0..127
    const int ah   = tid & 1;            // 64B half
    const int brow = tid >> 4;           // B row 0..15
    const int bc   = tid & 15;           // 64B chunk (8 float2)

    const float2* Ag = A2 + (size_t)(by * 128 + am) * 512 + ah * 8;
    const float2* Bg = B2 + (size_t)brow * N + bx * 128 + bc * 8;
    const uint32_t a_sdst = sbase + (am * AST + ah * 8) * 8;
    const uint32_t b_sdst = sbase + (A_STG_F2 + brow * BST + bc * 8) * 8;

    auto load_stage = [&](int t) {
        const uint32_t so = (t % NST) * STG_BYTES;
        const float2* ag = Ag + t * 16;
        #pragma unroll
        for (int c = 0; c < 4; c++)
            cp_async16(a_sdst + so + c * 16, ag + c * 2);
        const float2* bg = Bg + (size_t)(t * 16) * N;
        #pragma unroll
        for (int c = 0; c < 4; c++)
            cp_async16(b_sdst + so + c * 16, bg + c * 2);
    };

    float acc[4][4][4];
    #pragma unroll
    for (int i = 0; i < 4; i++)
        #pragma unroll
        for (int j = 0; j < 4; j++)
            #pragma unroll
            for (int r = 0; r < 4; r++) acc[i][j][r] = 0.f;

    load_stage(0);
    asm volatile("cp.async.commit_group;" ::: "memory");
    load_stage(1);
    asm volatile("cp.async.commit_group;" ::: "memory");

    for (int t = 0; t < 32; t++) {
        asm volatile("cp.async.wait_group 1;" ::: "memory");
        __syncthreads();

        if (t + 2 < 32) load_stage(t + 2);
        asm volatile("cp.async.commit_group;" ::: "memory");

        const float2* As = (const float2*)(smem + (t % NST) * STG_BYTES);
        const float2* Bs = As + A_STG_F2;

        #pragma unroll
        for (int ks = 0; ks < 4; ks++) {
            uint32_t af[4][4], bf[4][2];
            #pragma unroll
            for (int i = 0; i < 4; i++) {
                const int rbase = wm * 64 + i * 16 + r0;
                const float2 a02 = As[rbase * AST + ks * 4 + c0];
                const float2 a13 = As[(rbase + 8) * AST + ks * 4 + c0];
                af[i][0] = __float_as_uint(a02.x);
                af[i][1] = __float_as_uint(a13.x);
                af[i][2] = __float_as_uint(a02.y);
                af[i][3] = __float_as_uint(a13.y);
            }
            #pragma unroll
            for (int j = 0; j < 4; j++) {
                const float2 b01 =
                    Bs[(ks * 4 + c0) * BST + wn * 32 + j * 8 + r0];
                bf[j][0] = __float_as_uint(b01.x);
                bf[j][1] = __float_as_uint(b01.y);
            }
            #pragma unroll
            for (int i = 0; i < 4; i++)
                #pragma unroll
                for (int j = 0; j < 4; j++)
                    mma_tf32(acc[i][j], af[i], bf[j]);
        }
    }

    // Epilogue: add bias, write C
    #pragma unroll
    for (int i = 0; i < 4; i++) {
        const int row0 = by * 128 + wm * 64 + i * 16 + r0;
        #pragma unroll
        for (int j = 0; j < 4; j++) {
            const int col = bx * 128 + wn * 32 + j * 8 + 2 * c0;
            const float2 bv = *(const float2*)&bias[col];
            float2 o0, o1;
            o0.x = acc[i][j][0] + bv.x;
            o0.y = acc[i][j][1] + bv.y;
            o1.x = acc[i][j][2] + bv.x;
            o1.y = acc[i][j][3] + bv.y;
            *(float2*)&C[(size_t)row0 * N + col] = o0;
            *(float2*)&C[(size_t)(row0 + 8) * N + col] = o1;
        }
    }
}

// ---------------------------------------------------------------------------
// Fused causal attention (flash-style online softmax), fp32. Unchanged.
// ---------------------------------------------------------------------------
__global__ void __launch_bounds__(128) attention_kernel(
    const float* __restrict__ qkv, const float* __restrict__ mask,
    float* __restrict__ out)
{
    const int qt  = blockIdx.x;
    const int h   = blockIdx.y;
    const int b   = blockIdx.z;
    const int tid = threadIdx.x;
    const int tx  = tid & 15;
    const int ty  = tid >> 4;

    __shared__ float Qt[64][64];
    __shared__ float KV[64][64];
    __shared__ float Ps[64][64];

    const int q0 = qt * 64;
    const float* qbase = qkv + (size_t)(b * 512) * 3072 + h * 64;
    const float* kbase = qbase + 1024;
    const float* vbase = qbase + 2048;

    for (int t = tid; t < 64 * 16; t += 128) {
        const int r = t >> 4;
        const int c = (t & 15) << 2;
        float4 v = *(const float4*)(qbase + (size_t)(q0 + r) * 3072 + c);
        Qt[c + 0][r] = v.x; Qt[c + 1][r] = v.y;
        Qt[c + 2][r] = v.z; Qt[c + 3][r] = v.w;
    }

    float acc[8][4];
    float mrun[8], lrun[8];
    #pragma unroll
    for (int i = 0; i < 8; i++) {
        mrun[i] = -1e30f;
        lrun[i] = 0.f;
        #pragma unroll
        for (int j = 0; j < 4; j++) acc[i][j] = 0.f;
    }

    for (int kt = 0; kt <= qt; kt++) {
        const int k0 = kt * 64;

        __syncthreads();
        for (int t = tid; t < 64 * 16; t += 128) {
            const int r = t >> 4;
            const int c = (t & 15) << 2;
            float4 v = *(const float4*)(kbase + (size_t)(k0 + r) * 3072 + c);
            KV[c + 0][r] = v.x; KV[c + 1][r] = v.y;
            KV[c + 2][r] = v.z; KV[c + 3][r] = v.w;
        }
        __syncthreads();

        float s[8][4];
        #pragma unroll
        for (int i = 0; i < 8; i++)
            #pragma unroll
            for (int j = 0; j < 4; j++) s[i][j] = 0.f;

        #pragma unroll 8
        for (int d = 0; d < 64; d++) {
            float qr[8];
            *(float4*)&qr[0] = *(const float4*)&Qt[d][ty * 8];
            *(float4*)&qr[4] = *(const float4*)&Qt[d][ty * 8 + 4];
            const float4 kv = *(const float4*)&KV[d][tx * 4];
            #pragma unroll
            for (int i = 0; i < 8; i++) {
                s[i][0] += qr[i] * kv.x;
                s[i][1] += qr[i] * kv.y;
                s[i][2] += qr[i] * kv.z;
                s[i][3] += qr[i] * kv.w;
            }
        }
        __syncthreads();

        for (int t = tid; t < 64 * 16; t += 128) {
            const int r = t >> 4;
            const int c = (t & 15) << 2;
            *(float4*)&KV[r][c] =
                *(const float4*)(vbase + (size_t)(k0 + r) * 3072 + c);
        }

        float mk[4];
        #pragma unroll
        for (int j = 0; j < 4; j++)
            mk[j] = mask[b * 512 + k0 + tx * 4 + j];

        #pragma unroll
        for (int i = 0; i < 8; i++) {
            const int qg = q0 + ty * 8 + i;
            float rmax = -1e30f;
            #pragma unroll
            for (int j = 0; j < 4; j++) {
                const int kg = k0 + tx * 4 + j;
                const float bm = (kg <= qg) ? mk[j] : 0.f;
                float v = s[i][j] * 0.125f;
                v = v * bm - 1e9f * (1.f - bm);
                s[i][j] = v;
                rmax = fmaxf(rmax, v);
            }
            #pragma unroll
            for (int o = 8; o >= 1; o >>= 1)
                rmax = fmaxf(rmax, __shfl_xor_sync(0xffffffffu, rmax, o));
            const float mnew  = fmaxf(mrun[i], rmax);
            const float alpha = __expf(mrun[i] - mnew);
            mrun[i] = mnew;
            lrun[i] *= alpha;
            #pragma unroll
            for (int j = 0; j < 4; j++) acc[i][j] *= alpha;
            float4 p;
            p.x = __expf(s[i][0] - mnew);
            p.y = __expf(s[i][1] - mnew);
            p.z = __expf(s[i][2] - mnew);
            p.w = __expf(s[i][3] - mnew);
            float psum = p.x + p.y + p.z + p.w;
            #pragma unroll
            for (int o = 8; o >= 1; o >>= 1)
                psum += __shfl_xor_sync(0xffffffffu, psum, o);
            lrun[i] += psum;
            *(float4*)&Ps[ty * 8 + i][tx * 4] = p;
        }
        __syncthreads();

        #pragma unroll 8
        for (int kk = 0; kk < 64; kk++) {
            const float4 vv = *(const float4*)&KV[kk][tx * 4];
            #pragma unroll
            for (int i = 0; i < 8; i++) {
                const float p = Ps[ty * 8 + i][kk];
                acc[i][0] += p * vv.x;
                acc[i][1] += p * vv.y;
                acc[i][2] += p * vv.z;
                acc[i][3] += p * vv.w;
            }
        }
    }

    #pragma unroll
    for (int i = 0; i < 8; i++) {
        const float invl = 1.f / lrun[i];
        const int qg = q0 + ty * 8 + i;
        float4 o;
        o.x = acc[i][0] * invl;
        o.y = acc[i][1] * invl;
        o.z = acc[i][2] * invl;
        o.w = acc[i][3] * invl;
        *(float4*)&out[(size_t)(b * 512 + qg) * 1024 + h * 64 + tx * 4] = o;
    }
}

// ---------------------------------------------------------------------------
// Launch
// ---------------------------------------------------------------------------
extern "C" void kernel_launch(void* const* d_in, const int* in_sizes, int n_in,
                              void* d_out, int out_size)
{
    const float* x        = (const float*)d_in[0];
    const float* mask     = (const float*)d_in[1];
    const float* c_attn_w = (const float*)d_in[2];
    const float* c_attn_b = (const float*)d_in[3];
    const float* c_proj_w = (const float*)d_in[4];
    const float* c_proj_b = (const float*)d_in[5];
    float* out = (float*)d_out;

    float *qkv_ptr = nullptr, *attn_ptr = nullptr;
    float2 *a2_ptr = nullptr, *w2_ptr = nullptr;
    cudaGetSymbolAddress((void**)&qkv_ptr, g_qkv);
    cudaGetSymbolAddress((void**)&attn_ptr, g_attn);
    cudaGetSymbolAddress((void**)&a2_ptr, g_a2);
    cudaGetSymbolAddress((void**)&w2_ptr, g_w2);
    float2* w2_qkv  = w2_ptr;
    float2* w2_proj = w2_ptr + (size_t)512 * 3072;

    cudaFuncSetAttribute(gemm_tf32i_kernel,
                         cudaFuncAttributeMaxDynamicSharedMemorySize,
                         GEMM_DSMEM);

    // 0. Prep weights + x (tf32, pair-interleaved)
    prep_W_kernel<<<512 * (3072 / 4) / 256, 256>>>(c_attn_w, w2_qkv, 3072);
    prep_W_kernel<<<512 * (1024 / 4) / 256, 256>>>(c_proj_w, w2_proj, 1024);
    prep_A_kernel<<<4096 * 128 / 256, 256>>>(x, a2_ptr);

    // 1. QKV projection
    gemm_tf32i_kernel<<<dim3(3072 / 128, 4096 / 128), 256, GEMM_DSMEM>>>(
        a2_ptr, w2_qkv, c_attn_b, qkv_ptr, 3072);

    // 2. Fused causal attention
    attention_kernel<<<dim3(512 / 64, 16, 8), 128>>>(qkv_ptr, mask, attn_ptr);

    // 3. Prep attention output, then output projection
    prep_A_kernel<<<4096 * 128 / 256, 256>>>(attn_ptr, a2_ptr);
    gemm_tf32i_kernel<<<dim3(1024 / 128, 4096 / 128), 256, GEMM_DSMEM>>>(
        a2_ptr, w2_proj, c_proj_b, out, 1024);
}

// round 12
// speedup vs baseline: 1.0143x; 1.0143x over previous
#include <cuda_runtime.h>
#include <cstdint>

// ---------------------------------------------------------------------------
// Scratch (allocation-free: __device__ globals)
// ---------------------------------------------------------------------------
__device__ float  g_qkv[8 * 512 * 3072];          // [B*S, 3D] fp32
__device__ float  g_attn[8 * 512 * 1024];         // [B*S, D]  fp32
__device__ float2 g_a2[4096 * 512];               // A operand, tf32 pair-interleaved
__device__ float2 g_w2[512 * 3072 + 512 * 1024];  // W operands, tf32 pair-interleaved

static __device__ __forceinline__ float cvt_rna_f(float x) {
    uint32_t r;
    asm("cvt.rna.tf32.f32 %0, %1;" : "=r"(r) : "f"(x));
    return __uint_as_float(r);
}

// ---------------------------------------------------------------------------
// prep_A: A[M,1024] fp32 -> A2[M,512] float2, A2[m][g*4+c] = tf32(A[m][g*8+c],
// A[m][g*8+c+4]).  One thread per (m, g) 8-k group.
// ---------------------------------------------------------------------------
__global__ void __launch_bounds__(256) prep_A_kernel(
    const float* __restrict__ A, float2* __restrict__ A2)
{
    const int t = blockIdx.x * 256 + threadIdx.x;
    const int m = t >> 7, g = t & 127;
    const float4 lo = *(const float4*)(A + (size_t)m * 1024 + g * 8);
    const float4 hi = *(const float4*)(A + (size_t)m * 1024 + g * 8 + 4);
    float2* o = A2 + (size_t)m * 512 + g * 4;
    o[0] = make_float2(cvt_rna_f(lo.x), cvt_rna_f(hi.x));
    o[1] = make_float2(cvt_rna_f(lo.y), cvt_rna_f(hi.y));
    o[2] = make_float2(cvt_rna_f(lo.z), cvt_rna_f(hi.z));
    o[3] = make_float2(cvt_rna_f(lo.w), cvt_rna_f(hi.w));
}

// ---------------------------------------------------------------------------
// prep_W: W[1024,N] fp32 -> B2[512,N] float2,
// B2[p][n] = tf32(W[klo][n], W[klo+4][n]), klo = (p/4)*8 + p%4.
// ---------------------------------------------------------------------------
__global__ void __launch_bounds__(256) prep_W_kernel(
    const float* __restrict__ W, float2* __restrict__ B2, int N)
{
    const int t = blockIdx.x * 256 + threadIdx.x;
    const int nq = N >> 2;
    const int p = t / nq, n4 = (t % nq) << 2;
    const int klo = ((p >> 2) << 3) + (p & 3);
    const float4 lo = *(const float4*)(W + (size_t)klo * N + n4);
    const float4 hi = *(const float4*)(W + (size_t)(klo + 4) * N + n4);
    float2* o = B2 + (size_t)p * N + n4;
    o[0] = make_float2(cvt_rna_f(lo.x), cvt_rna_f(hi.x));
    o[1] = make_float2(cvt_rna_f(lo.y), cvt_rna_f(hi.y));
    o[2] = make_float2(cvt_rna_f(lo.z), cvt_rna_f(hi.z));
    o[3] = make_float2(cvt_rna_f(lo.w), cvt_rna_f(hi.w));
}

// ---------------------------------------------------------------------------
// TF32 mma.sync GEMM, pair-interleaved operands, 64x64 warp tiles.
// C[M,N] = A[M,1024] @ W[1024,N] + bias[N]
// CTA tile 128x256x32, 256 thr (8 warps, 2x4), warp tile 64x64, m16n8k8.
// 3-stage cp.async pipeline, one __syncthreads per iter.
// Per warp-iter: 64 LDS.64 feed 128 MMAs (0.5 LDS/MMA).
// ---------------------------------------------------------------------------
#define AST 20                     // A stage row stride (float2)
#define BST 260                    // B stage row stride (float2); 520 banks = 8 mod 32
#define A_STG_F2 (128 * AST)       // 2560 float2
#define B_STG_F2 (16 * BST)        // 4160 float2
#define STG_BYTES ((A_STG_F2 + B_STG_F2) * 8)   // 53760 B
#define NST 3
#define GEMM_DSMEM (NST * STG_BYTES)            // 161280 B

static __device__ __forceinline__ void cp_async16(uint32_t s, const void* g) {
    asm volatile("cp.async.cg.shared.global [%0], [%1], 16;\n"
                 :: "r"(s), "l"(g) : "memory");
}

static __device__ __forceinline__ void mma_tf32(float* c, const uint32_t* a,
                                                const uint32_t* b) {
    asm volatile(
        "mma.sync.aligned.m16n8k8.row.col.f32.tf32.tf32.f32 "
        "{%0,%1,%2,%3}, {%4,%5,%6,%7}, {%8,%9}, {%0,%1,%2,%3};"
        : "+f"(c[0]), "+f"(c[1]), "+f"(c[2]), "+f"(c[3])
        : "r"(a[0]), "r"(a[1]), "r"(a[2]), "r"(a[3]), "r"(b[0]), "r"(b[1]));
}

__global__ void __launch_bounds__(256, 1) gemm_tf32w_kernel(
    const float2* __restrict__ A2, const float2* __restrict__ B2,
    const float* __restrict__ bias, float* __restrict__ C, int N)
{
    extern __shared__ char smem[];
    const int tid  = threadIdx.x;
    const int lane = tid & 31;
    const int warp = tid >> 5;
    const int wm   = warp >> 2;          // 0..1  (64 rows)
    const int wn   = warp & 3;           // 0..3  (64 cols)
    const int bx   = blockIdx.x, by = blockIdx.y;
    const int r0   = lane >> 2;          // 0..7
    const int c0   = lane & 3;           // 0..3

    uint32_t sbase;
    asm("{ .reg .u64 t; cvta.to.shared.u64 t, %1; cvt.u32.u64 %0, t; }"
        : "=r"(sbase) : "l"(smem));

    // Copy mapping: per 32-k stage A = 16KB (64B/thread), B = 32KB (128B/thread)
    const int am   = tid >> 1;           // A row 0..127
    const int ah   = tid & 1;            // 64B half (8 float2)
    const int brow = tid >> 4;           // B row 0..15
    const int bc   = tid & 15;           // 128B chunk (16 float2)

    const float2* Ag = A2 + (size_t)(by * 128 + am) * 512 + ah * 8;
    const float2* Bg = B2 + (size_t)brow * N + bx * 256 + bc * 16;
    const uint32_t a_sdst = sbase + (am * AST + ah * 8) * 8;
    const uint32_t b_sdst = sbase + (A_STG_F2 + brow * BST + bc * 16) * 8;

    auto load_stage = [&](int t) {
        const uint32_t so = (t % NST) * STG_BYTES;
        const float2* ag = Ag + t * 16;
        #pragma unroll
        for (int c = 0; c < 4; c++)                       // 4 x 16B = 8 float2
            cp_async16(a_sdst + so + c * 16, ag + c * 2);
        const float2* bg = Bg + (size_t)(t * 16) * N;
        #pragma unroll
        for (int c = 0; c < 8; c++)                       // 8 x 16B = 16 float2
            cp_async16(b_sdst + so + c * 16, bg + c * 2);
    };

    float acc[4][8][4];
    #pragma unroll
    for (int i = 0; i < 4; i++)
        #pragma unroll
        for (int j = 0; j < 8; j++)
            #pragma unroll
            for (int r = 0; r < 4; r++) acc[i][j][r] = 0.f;

    load_stage(0);
    asm volatile("cp.async.commit_group;" ::: "memory");
    load_stage(1);
    asm volatile("cp.async.commit_group;" ::: "memory");

    for (int t = 0; t < 32; t++) {
        asm volatile("cp.async.wait_group 1;" ::: "memory");
        __syncthreads();

        if (t + 2 < 32) load_stage(t + 2);
        asm volatile("cp.async.commit_group;" ::: "memory");

        const float2* As = (const float2*)(smem + (t % NST) * STG_BYTES);
        const float2* Bs = As + A_STG_F2;

        #pragma unroll
        for (int ks = 0; ks < 4; ks++) {
            uint32_t af[4][4], bf[8][2];
            #pragma unroll
            for (int i = 0; i < 4; i++) {
                const int rbase = wm * 64 + i * 16 + r0;
                const float2 a02 = As[rbase * AST + ks * 4 + c0];
                const float2 a13 = As[(rbase + 8) * AST + ks * 4 + c0];
                af[i][0] = __float_as_uint(a02.x);
                af[i][1] = __float_as_uint(a13.x);
                af[i][2] = __float_as_uint(a02.y);
                af[i][3] = __float_as_uint(a13.y);
            }
            #pragma unroll
            for (int j = 0; j < 8; j++) {
                const float2 b01 =
                    Bs[(ks * 4 + c0) * BST + wn * 64 + j * 8 + r0];
                bf[j][0] = __float_as_uint(b01.x);
                bf[j][1] = __float_as_uint(b01.y);
            }
            #pragma unroll
            for (int i = 0; i < 4; i++)
                #pragma unroll
                for (int j = 0; j < 8; j++)
                    mma_tf32(acc[i][j], af[i], bf[j]);
        }
    }

    // Epilogue: add bias, write C
    #pragma unroll
    for (int i = 0; i < 4; i++) {
        const int row0 = by * 128 + wm * 64 + i * 16 + r0;
        #pragma unroll
        for (int j = 0; j < 8; j++) {
            const int col = bx * 256 + wn * 64 + j * 8 + 2 * c0;
            const float2 bv = *(const float2*)&bias[col];
            float2 o0, o1;
            o0.x = acc[i][j][0] + bv.x;
            o0.y = acc[i][j][1] + bv.y;
            o1.x = acc[i][j][2] + bv.x;
            o1.y = acc[i][j][3] + bv.y;
            *(float2*)&C[(size_t)row0 * N + col] = o0;
            *(float2*)&C[(size_t)(row0 + 8) * N + col] = o1;
        }
    }
}

// ---------------------------------------------------------------------------
// Fused causal attention (flash-style online softmax), fp32. Unchanged.
// ---------------------------------------------------------------------------
__global__ void __launch_bounds__(128) attention_kernel(
    const float* __restrict__ qkv, const float* __restrict__ mask,
    float* __restrict__ out)
{
    const int qt  = blockIdx.x;
    const int h   = blockIdx.y;
    const int b   = blockIdx.z;
    const int tid = threadIdx.x;
    const int tx  = tid & 15;
    const int ty  = tid >> 4;

    __shared__ float Qt[64][64];
    __shared__ float KV[64][64];
    __shared__ float Ps[64][64];

    const int q0 = qt * 64;
    const float* qbase = qkv + (size_t)(b * 512) * 3072 + h * 64;
    const float* kbase = qbase + 1024;
    const float* vbase = qbase + 2048;

    for (int t = tid; t < 64 * 16; t += 128) {
        const int r = t >> 4;
        const int c = (t & 15) << 2;
        float4 v = *(const float4*)(qbase + (size_t)(q0 + r) * 3072 + c);
        Qt[c + 0][r] = v.x; Qt[c + 1][r] = v.y;
        Qt[c + 2][r] = v.z; Qt[c + 3][r] = v.w;
    }

    float acc[8][4];
    float mrun[8], lrun[8];
    #pragma unroll
    for (int i = 0; i < 8; i++) {
        mrun[i] = -1e30f;
        lrun[i] = 0.f;
        #pragma unroll
        for (int j = 0; j < 4; j++) acc[i][j] = 0.f;
    }

    for (int kt = 0; kt <= qt; kt++) {
        const int k0 = kt * 64;

        __syncthreads();
        for (int t = tid; t < 64 * 16; t += 128) {
            const int r = t >> 4;
            const int c = (t & 15) << 2;
            float4 v = *(const float4*)(kbase + (size_t)(k0 + r) * 3072 + c);
            KV[c + 0][r] = v.x; KV[c + 1][r] = v.y;
            KV[c + 2][r] = v.z; KV[c + 3][r] = v.w;
        }
        __syncthreads();

        float s[8][4];
        #pragma unroll
        for (int i = 0; i < 8; i++)
            #pragma unroll
            for (int j = 0; j < 4; j++) s[i][j] = 0.f;

        #pragma unroll 8
        for (int d = 0; d < 64; d++) {
            float qr[8];
            *(float4*)&qr[0] = *(const float4*)&Qt[d][ty * 8];
            *(float4*)&qr[4] = *(const float4*)&Qt[d][ty * 8 + 4];
            const float4 kv = *(const float4*)&KV[d][tx * 4];
            #pragma unroll
            for (int i = 0; i < 8; i++) {
                s[i][0] += qr[i] * kv.x;
                s[i][1] += qr[i] * kv.y;
                s[i][2] += qr[i] * kv.z;
                s[i][3] += qr[i] * kv.w;
            }
        }
        __syncthreads();

        for (int t = tid; t < 64 * 16; t += 128) {
            const int r = t >> 4;
            const int c = (t & 15) << 2;
            *(float4*)&KV[r][c] =
                *(const float4*)(vbase + (size_t)(k0 + r) * 3072 + c);
        }

        float mk[4];
        #pragma unroll
        for (int j = 0; j < 4; j++)
            mk[j] = mask[b * 512 + k0 + tx * 4 + j];

        #pragma unroll
        for (int i = 0; i < 8; i++) {
            const int qg = q0 + ty * 8 + i;
            float rmax = -1e30f;
            #pragma unroll
            for (int j = 0; j < 4; j++) {
                const int kg = k0 + tx * 4 + j;
                const float bm = (kg <= qg) ? mk[j] : 0.f;
                float v = s[i][j] * 0.125f;
                v = v * bm - 1e9f * (1.f - bm);
                s[i][j] = v;
                rmax = fmaxf(rmax, v);
            }
            #pragma unroll
            for (int o = 8; o >= 1; o >>= 1)
                rmax = fmaxf(rmax, __shfl_xor_sync(0xffffffffu, rmax, o));
            const float mnew  = fmaxf(mrun[i], rmax);
            const float alpha = __expf(mrun[i] - mnew);
            mrun[i] = mnew;
            lrun[i] *= alpha;
            #pragma unroll
            for (int j = 0; j < 4; j++) acc[i][j] *= alpha;
            float4 p;
            p.x = __expf(s[i][0] - mnew);
            p.y = __expf(s[i][1] - mnew);
            p.z = __expf(s[i][2] - mnew);
            p.w = __expf(s[i][3] - mnew);
            float psum = p.x + p.y + p.z + p.w;
            #pragma unroll
            for (int o = 8; o >= 1; o >>= 1)
                psum += __shfl_xor_sync(0xffffffffu, psum, o);
            lrun[i] += psum;
            *(float4*)&Ps[ty * 8 + i][tx * 4] = p;
        }
        __syncthreads();

        #pragma unroll 8
        for (int kk = 0; kk < 64; kk++) {
            const float4 vv = *(const float4*)&KV[kk][tx * 4];
            #pragma unroll
            for (int i = 0; i < 8; i++) {
                const float p = Ps[ty * 8 + i][kk];
                acc[i][0] += p * vv.x;
                acc[i][1] += p * vv.y;
                acc[i][2] += p * vv.z;
                acc[i][3] += p * vv.w;
            }
        }
    }

    #pragma unroll
    for (int i = 0; i < 8; i++) {
        const float invl = 1.f / lrun[i];
        const int qg = q0 + ty * 8 + i;
        float4 o;
        o.x = acc[i][0] * invl;
        o.y = acc[i][1] * invl;
        o.z = acc[i][2] * invl;
        o.w = acc[i][3] * invl;
        *(float4*)&out[(size_t)(b * 512 + qg) * 1024 + h * 64 + tx * 4] = o;
    }
}

// ---------------------------------------------------------------------------
// Launch
// ---------------------------------------------------------------------------
extern "C" void kernel_launch(void* const* d_in, const int* in_sizes, int n_in,
                              void* d_out, int out_size)
{
    const float* x        = (const float*)d_in[0];
    const float* mask     = (const float*)d_in[1];
    const float* c_attn_w = (const float*)d_in[2];
    const float* c_attn_b = (const float*)d_in[3];
    const float* c_proj_w = (const float*)d_in[4];
    const float* c_proj_b = (const float*)d_in[5];
    float* out = (float*)d_out;

    float *qkv_ptr = nullptr, *attn_ptr = nullptr;
    float2 *a2_ptr = nullptr, *w2_ptr = nullptr;
    cudaGetSymbolAddress((void**)&qkv_ptr, g_qkv);
    cudaGetSymbolAddress((void**)&attn_ptr, g_attn);
    cudaGetSymbolAddress((void**)&a2_ptr, g_a2);
    cudaGetSymbolAddress((void**)&w2_ptr, g_w2);
    float2* w2_qkv  = w2_ptr;
    float2* w2_proj = w2_ptr + (size_t)512 * 3072;

    cudaFuncSetAttribute(gemm_tf32w_kernel,
                         cudaFuncAttributeMaxDynamicSharedMemorySize,
                         GEMM_DSMEM);

    // 0. Prep weights + x (tf32, pair-interleaved)
    prep_W_kernel<<<512 * (3072 / 4) / 256, 256>>>(c_attn_w, w2_qkv, 3072);
    prep_W_kernel<<<512 * (1024 / 4) / 256, 256>>>(c_proj_w, w2_proj, 1024);
    prep_A_kernel<<<4096 * 128 / 256, 256>>>(x, a2_ptr);

    // 1. QKV projection: CTA tile 128x256
    gemm_tf32w_kernel<<<dim3(3072 / 256, 4096 / 128), 256, GEMM_DSMEM>>>(
        a2_ptr, w2_qkv, c_attn_b, qkv_ptr, 3072);

    // 2. Fused causal attention
    attention_kernel<<<dim3(512 / 64, 16, 8), 128>>>(qkv_ptr, mask, attn_ptr);

    // 3. Prep attention output, then output projection
    prep_A_kernel<<<4096 * 128 / 256, 256>>>(attn_ptr, a2_ptr);
    gemm_tf32w_kernel<<<dim3(1024 / 256, 4096 / 128), 256, GEMM_DSMEM>>>(
        a2_ptr, w2_proj, c_proj_b, out, 1024);
}

// round 14
// speedup vs baseline: 1.4775x; 1.4566x over previous
#include <cuda_runtime.h>
#include <cuda_fp16.h>
#include <cstdint>

// ---------------------------------------------------------------------------
// Scratch (allocation-free: __device__ globals)
// ---------------------------------------------------------------------------
__device__ float   g_qkv[8 * 512 * 3072];     // [B*S, 3D] fp32
__device__ float   g_attn[8 * 512 * 1024];    // [B*S, D]  fp32
__device__ __half2 g_a2h[4096 * 512];         // A operand, fp16 frag-interleaved
__device__ uint2   g_w2h[256 * 4096];         // W operands (qkv 256x3072 | proj 256x1024)

// ---------------------------------------------------------------------------
// prep_A: A[M,1024] fp32 -> A2h[M,512] half2, fragment-native interleave.
// Group g (16 k): out[g*8+2c]   = h2(A[16g+2c],  A[16g+2c+1])
//                 out[g*8+2c+1] = h2(A[16g+2c+8],A[16g+2c+9]),  c=0..3
// One thread per (m, g).
// ---------------------------------------------------------------------------
__global__ void __launch_bounds__(256) prep_A_h_kernel(
    const float* __restrict__ A, __half2* __restrict__ A2)
{
    const int t = blockIdx.x * 256 + threadIdx.x;
    const int m = t >> 6, g = t & 63;
    const float* a = A + (size_t)m * 1024 + g * 16;
    float f[16];
    #pragma unroll
    for (int c = 0; c < 4; c++)
        *(float4*)&f[c * 4] = *(const float4*)(a + c * 4);
    __half2* o = A2 + (size_t)m * 512 + g * 8;
    #pragma unroll
    for (int c = 0; c < 4; c++) {
        o[2 * c]     = __halves2half2(__float2half_rn(f[2 * c]),
                                      __float2half_rn(f[2 * c + 1]));
        o[2 * c + 1] = __halves2half2(__float2half_rn(f[2 * c + 8]),
                                      __float2half_rn(f[2 * c + 9]));
    }
}

// ---------------------------------------------------------------------------
// prep_W: W[1024,N] fp32 -> Bh[256,N] uint2 (B fragment pairs).
// Row p = g*4+c (g = k/16, c = 0..3):
//   Bh[p][n] = { h2(W[16g+2c][n], W[16g+2c+1][n]),
//                h2(W[16g+2c+8][n], W[16g+2c+9][n]) }
// One thread per (p, 4-n chunk).
// ---------------------------------------------------------------------------
__global__ void __launch_bounds__(256) prep_W_h_kernel(
    const float* __restrict__ W, uint2* __restrict__ Bh, int N)
{
    const int t = blockIdx.x * 256 + threadIdx.x;
    const int nq = N >> 2;
    const int p = t / nq, n4 = (t % nq) << 2;
    const int k0 = ((p >> 2) << 4) + ((p & 3) << 1);
    const float4 w0 = *(const float4*)(W + (size_t)k0 * N + n4);
    const float4 w1 = *(const float4*)(W + (size_t)(k0 + 1) * N + n4);
    const float4 w8 = *(const float4*)(W + (size_t)(k0 + 8) * N + n4);
    const float4 w9 = *(const float4*)(W + (size_t)(k0 + 9) * N + n4);
    uint2* o = Bh + (size_t)p * N + n4;
    const float* p0 = (const float*)&w0;
    const float* p1 = (const float*)&w1;
    const float* p8 = (const float*)&w8;
    const float* p9 = (const float*)&w9;
    #pragma unroll
    for (int n = 0; n < 4; n++) {
        __half2 lo = __halves2half2(__float2half_rn(p0[n]), __float2half_rn(p1[n]));
        __half2 hi = __halves2half2(__float2half_rn(p8[n]), __float2half_rn(p9[n]));
        uint2 v;
        v.x = *(uint32_t*)&lo;
        v.y = *(uint32_t*)&hi;
        o[n] = v;
    }
}

// ---------------------------------------------------------------------------
// FP16 mma.sync GEMM (m16n8k16, fp32 accum), 64x64 warp tiles.
// C[M,N] = A[M,1024] @ W[1024,N] + bias[N]
// CTA tile 128x256x32, 256 thr (8 warps, 2x4), 3-stage cp.async pipeline.
// Per warp-iter (k32): 32 LDS.64 feed 128 MMAs.
// ---------------------------------------------------------------------------
#define ASTH 24                    // A row stride in half2 (16 data + 8 pad): 96B
#define BST8 260                   // B p-row stride in uint2: 2080B
#define A_STG (128 * ASTH * 4)     // 12288 B
#define B_STG (8 * BST8 * 8)       // 16640 B
#define STG_BYTES (A_STG + B_STG)  // 28928 B
#define NST 3
#define GEMM_DSMEM (NST * STG_BYTES)   // 86784 B

static __device__ __forceinline__ void cp_async16(uint32_t s, const void* g) {
    asm volatile("cp.async.cg.shared.global [%0], [%1], 16;\n"
                 :: "r"(s), "l"(g) : "memory");
}

static __device__ __forceinline__ void mma_f16(float* c, uint32_t a0, uint32_t a1,
                                               uint32_t a2, uint32_t a3,
                                               uint32_t b0, uint32_t b1) {
    asm volatile(
        "mma.sync.aligned.m16n8k16.row.col.f32.f16.f16.f32 "
        "{%0,%1,%2,%3}, {%4,%5,%6,%7}, {%8,%9}, {%0,%1,%2,%3};"
        : "+f"(c[0]), "+f"(c[1]), "+f"(c[2]), "+f"(c[3])
        : "r"(a0), "r"(a1), "r"(a2), "r"(a3), "r"(b0), "r"(b1));
}

__global__ void __launch_bounds__(256, 1) gemm_f16_kernel(
    const __half2* __restrict__ A2, const uint2* __restrict__ B2,
    const float* __restrict__ bias, float* __restrict__ C, int N)
{
    extern __shared__ char smem[];
    const int tid  = threadIdx.x;
    const int lane = tid & 31;
    const int warp = tid >> 5;
    const int wm   = warp >> 2;          // 0..1  (64 rows)
    const int wn   = warp & 3;           // 0..3  (64 cols)
    const int bx   = blockIdx.x, by = blockIdx.y;
    const int r0   = lane >> 2;          // 0..7
    const int c0   = lane & 3;           // 0..3

    uint32_t sbase;
    asm("{ .reg .u64 t; cvta.to.shared.u64 t, %1; cvt.u32.u64 %0, t; }"
        : "=r"(sbase) : "l"(smem));

    // Copy mapping: per stage A = 8KB (32B/thread), B = 16KB (64B/thread)
    const int am = tid >> 1, ah = tid & 1;     // A row, 32B half
    const int bp = tid >> 5, bn = tid & 31;    // B p-row, 64B chunk

    const __half2* Ag = A2 + (size_t)(by * 128 + am) * 512 + ah * 8;
    const uint2*   Bg = B2 + (size_t)bp * N + bx * 256 + bn * 8;
    const uint32_t a_sdst = sbase + am * (ASTH * 4) + ah * 32;
    const uint32_t b_sdst = sbase + A_STG + bp * (BST8 * 8) + bn * 64;

    auto load_stage = [&](int t) {
        const uint32_t so = (t % NST) * STG_BYTES;
        const __half2* ag = Ag + t * 16;
        #pragma unroll
        for (int c = 0; c < 2; c++)                      // 2 x 16B = 8 half2
            cp_async16(a_sdst + so + c * 16, ag + c * 4);
        const uint2* bg = Bg + (size_t)(t * 8) * N;
        #pragma unroll
        for (int c = 0; c < 4; c++)                      // 4 x 16B = 8 uint2
            cp_async16(b_sdst + so + c * 16, bg + c * 2);
    };

    float acc[4][8][4];
    #pragma unroll
    for (int i = 0; i < 4; i++)
        #pragma unroll
        for (int j = 0; j < 8; j++)
            #pragma unroll
            for (int r = 0; r < 4; r++) acc[i][j][r] = 0.f;

    load_stage(0);
    asm volatile("cp.async.commit_group;" ::: "memory");
    load_stage(1);
    asm volatile("cp.async.commit_group;" ::: "memory");

    for (int t = 0; t < 32; t++) {
        asm volatile("cp.async.wait_group 1;" ::: "memory");
        __syncthreads();

        if (t + 2 < 32) load_stage(t + 2);
        asm volatile("cp.async.commit_group;" ::: "memory");

        const uint32_t so = (t % NST) * STG_BYTES;
        const __half2* As = (const __half2*)(smem + so);
        const uint2*   Bs = (const uint2*)(smem + so + A_STG);

        #pragma unroll
        for (int ks = 0; ks < 2; ks++) {       // 2 x k16
            uint2 afl[4], afh[4], bf[8];
            #pragma unroll
            for (int i = 0; i < 4; i++) {
                const int rbase = wm * 64 + i * 16 + r0;
                const int idx = rbase * ASTH + ks * 8 + c0 * 2;
                afl[i] = *(const uint2*)(As + idx);
                afh[i] = *(const uint2*)(As + idx + 8 * ASTH);
            }
            #pragma unroll
            for (int j = 0; j < 8; j++)
                bf[j] = Bs[(ks * 4 + c0) * BST8 + wn * 64 + j * 8 + r0];
            #pragma unroll
            for (int i = 0; i < 4; i++)
                #pragma unroll
                for (int j = 0; j < 8; j++)
                    mma_f16(acc[i][j], afl[i].x, afh[i].x, afl[i].y, afh[i].y,
                            bf[j].x, bf[j].y);
        }
    }

    // Epilogue: add bias, write C
    #pragma unroll
    for (int i = 0; i < 4; i++) {
        const int row0 = by * 128 + wm * 64 + i * 16 + r0;
        #pragma unroll
        for (int j = 0; j < 8; j++) {
            const int col = bx * 256 + wn * 64 + j * 8 + 2 * c0;
            const float2 bv = *(const float2*)&bias[col];
            float2 o0, o1;
            o0.x = acc[i][j][0] + bv.x;
            o0.y = acc[i][j][1] + bv.y;
            o1.x = acc[i][j][2] + bv.x;
            o1.y = acc[i][j][3] + bv.y;
            *(float2*)&C[(size_t)row0 * N + col] = o0;
            *(float2*)&C[(size_t)(row0 + 8) * N + col] = o1;
        }
    }
}

// ---------------------------------------------------------------------------
// Fused causal attention (flash-style online softmax), fp32. Unchanged.
// ---------------------------------------------------------------------------
__global__ void __launch_bounds__(128) attention_kernel(
    const float* __restrict__ qkv, const float* __restrict__ mask,
    float* __restrict__ out)
{
    const int qt  = blockIdx.x;
    const int h   = blockIdx.y;
    const int b   = blockIdx.z;
    const int tid = threadIdx.x;
    const int tx  = tid & 15;
    const int ty  = tid >> 4;

    __shared__ float Qt[64][64];
    __shared__ float KV[64][64];
    __shared__ float Ps[64][64];

    const int q0 = qt * 64;
    const float* qbase = qkv + (size_t)(b * 512) * 3072 + h * 64;
    const float* kbase = qbase + 1024;
    const float* vbase = qbase + 2048;

    for (int t = tid; t < 64 * 16; t += 128) {
        const int r = t >> 4;
        const int c = (t & 15) << 2;
        float4 v = *(const float4*)(qbase + (size_t)(q0 + r) * 3072 + c);
        Qt[c + 0][r] = v.x; Qt[c + 1][r] = v.y;
        Qt[c + 2][r] = v.z; Qt[c + 3][r] = v.w;
    }

    float acc[8][4];
    float mrun[8], lrun[8];
    #pragma unroll
    for (int i = 0; i < 8; i++) {
        mrun[i] = -1e30f;
        lrun[i] = 0.f;
        #pragma unroll
        for (int j = 0; j < 4; j++) acc[i][j] = 0.f;
    }

    for (int kt = 0; kt <= qt; kt++) {
        const int k0 = kt * 64;

        __syncthreads();
        for (int t = tid; t < 64 * 16; t += 128) {
            const int r = t >> 4;
            const int c = (t & 15) << 2;
            float4 v = *(const float4*)(kbase + (size_t)(k0 + r) * 3072 + c);
            KV[c + 0][r] = v.x; KV[c + 1][r] = v.y;
            KV[c + 2][r] = v.z; KV[c + 3][r] = v.w;
        }
        __syncthreads();

        float s[8][4];
        #pragma unroll
        for (int i = 0; i < 8; i++)
            #pragma unroll
            for (int j = 0; j < 4; j++) s[i][j] = 0.f;

        #pragma unroll 8
        for (int d = 0; d < 64; d++) {
            float qr[8];
            *(float4*)&qr[0] = *(const float4*)&Qt[d][ty * 8];
            *(float4*)&qr[4] = *(const float4*)&Qt[d][ty * 8 + 4];
            const float4 kv = *(const float4*)&KV[d][tx * 4];
            #pragma unroll
            for (int i = 0; i < 8; i++) {
                s[i][0] += qr[i] * kv.x;
                s[i][1] += qr[i] * kv.y;
                s[i][2] += qr[i] * kv.z;
                s[i][3] += qr[i] * kv.w;
            }
        }
        __syncthreads();

        for (int t = tid; t < 64 * 16; t += 128) {
            const int r = t >> 4;
            const int c = (t & 15) << 2;
            *(float4*)&KV[r][c] =
                *(const float4*)(vbase + (size_t)(k0 + r) * 3072 + c);
        }

        float mk[4];
        #pragma unroll
        for (int j = 0; j < 4; j++)
            mk[j] = mask[b * 512 + k0 + tx * 4 + j];

        #pragma unroll
        for (int i = 0; i < 8; i++) {
            const int qg = q0 + ty * 8 + i;
            float rmax = -1e30f;
            #pragma unroll
            for (int j = 0; j < 4; j++) {
                const int kg = k0 + tx * 4 + j;
                const float bm = (kg <= qg) ? mk[j] : 0.f;
                float v = s[i][j] * 0.125f;
                v = v * bm - 1e9f * (1.f - bm);
                s[i][j] = v;
                rmax = fmaxf(rmax, v);
            }
            #pragma unroll
            for (int o = 8; o >= 1; o >>= 1)
                rmax = fmaxf(rmax, __shfl_xor_sync(0xffffffffu, rmax, o));
            const float mnew  = fmaxf(mrun[i], rmax);
            const float alpha = __expf(mrun[i] - mnew);
            mrun[i] = mnew;
            lrun[i] *= alpha;
            #pragma unroll
            for (int j = 0; j < 4; j++) acc[i][j] *= alpha;
            float4 p;
            p.x = __expf(s[i][0] - mnew);
            p.y = __expf(s[i][1] - mnew);
            p.z = __expf(s[i][2] - mnew);
            p.w = __expf(s[i][3] - mnew);
            float psum = p.x + p.y + p.z + p.w;
            #pragma unroll
            for (int o = 8; o >= 1; o >>= 1)
                psum += __shfl_xor_sync(0xffffffffu, psum, o);
            lrun[i] += psum;
            *(float4*)&Ps[ty * 8 + i][tx * 4] = p;
        }
        __syncthreads();

        #pragma unroll 8
        for (int kk = 0; kk < 64; kk++) {
            const float4 vv = *(const float4*)&KV[kk][tx * 4];
            #pragma unroll
            for (int i = 0; i < 8; i++) {
                const float p = Ps[ty * 8 + i][kk];
                acc[i][0] += p * vv.x;
                acc[i][1] += p * vv.y;
                acc[i][2] += p * vv.z;
                acc[i][3] += p * vv.w;
            }
        }
    }

    #pragma unroll
    for (int i = 0; i < 8; i++) {
        const float invl = 1.f / lrun[i];
        const int qg = q0 + ty * 8 + i;
        float4 o;
        o.x = acc[i][0] * invl;
        o.y = acc[i][1] * invl;
        o.z = acc[i][2] * invl;
        o.w = acc[i][3] * invl;
        *(float4*)&out[(size_t)(b * 512 + qg) * 1024 + h * 64 + tx * 4] = o;
    }
}

// ---------------------------------------------------------------------------
// Launch
// ---------------------------------------------------------------------------
extern "C" void kernel_launch(void* const* d_in, const int* in_sizes, int n_in,
                              void* d_out, int out_size)
{
    const float* x        = (const float*)d_in[0];
    const float* mask     = (const float*)d_in[1];
    const float* c_attn_w = (const float*)d_in[2];
    const float* c_attn_b = (const float*)d_in[3];
    const float* c_proj_w = (const float*)d_in[4];
    const float* c_proj_b = (const float*)d_in[5];
    float* out = (float*)d_out;

    float *qkv_ptr = nullptr, *attn_ptr = nullptr;
    __half2* a2_ptr = nullptr;
    uint2* w2_ptr = nullptr;
    cudaGetSymbolAddress((void**)&qkv_ptr, g_qkv);
    cudaGetSymbolAddress((void**)&attn_ptr, g_attn);
    cudaGetSymbolAddress((void**)&a2_ptr, g_a2h);
    cudaGetSymbolAddress((void**)&w2_ptr, g_w2h);
    uint2* w2_qkv  = w2_ptr;
    uint2* w2_proj = w2_ptr + (size_t)256 * 3072;

    cudaFuncSetAttribute(gemm_f16_kernel,
                         cudaFuncAttributeMaxDynamicSharedMemorySize,
                         GEMM_DSMEM);

    // 0. Prep weights + x (fp16, fragment-interleaved)
    prep_W_h_kernel<<<256 * (3072 / 4) / 256, 256>>>(c_attn_w, w2_qkv, 3072);
    prep_W_h_kernel<<<256 * (1024 / 4) / 256, 256>>>(c_proj_w, w2_proj, 1024);
    prep_A_h_kernel<<<4096 * 64 / 256, 256>>>(x, a2_ptr);

    // 1. QKV projection: CTA tile 128x256
    gemm_f16_kernel<<<dim3(3072 / 256, 4096 / 128), 256, GEMM_DSMEM>>>(
        a2_ptr, w2_qkv, c_attn_b, qkv_ptr, 3072);

    // 2. Fused causal attention
    attention_kernel<<<dim3(512 / 64, 16, 8), 128>>>(qkv_ptr, mask, attn_ptr);

    // 3. Prep attention output, then output projection
    prep_A_h_kernel<<<4096 * 64 / 256, 256>>>(attn_ptr, a2_ptr);
    gemm_f16_kernel<<<dim3(1024 / 256, 4096 / 128), 256, GEMM_DSMEM>>>(
        a2_ptr, w2_proj, c_proj_b, out, 1024);
}